// round 7
// baseline (speedup 1.0000x reference)
#include <cuda_runtime.h>

// Problem constants
#define CC   256      // channels (in == out)
#define HWP  4096     // 64*64 pixels
#define BM   128      // CTA tile M (out channels)
#define BN   128      // CTA tile N (pixels)
#define BK   32       // CTA tile K
#define LDA  136      // padded smem row stride (136 mod 32 == 8 -> conflict-free frags)
#define NKT  72       // 2304 / 32 K-tiles
#define STAGE_F (2*BK*LDA)           // floats per pipeline stage (A tile + B tile)
#define SMEM_BYTES (2*STAGE_F*4)     // 2 stages = 69632 B (dynamic, opt-in)

// Scratch (allocation-free rule: __device__ globals)
__device__ float g_W2[9*256*256];    // W transposed to [t][i][o], pre-rounded to tf32
__device__ float g_mask[64*9];       // per-batch softmax over 9 taps

__device__ __forceinline__ unsigned smem_u32(const void* p){
    return (unsigned)__cvta_generic_to_shared(p);
}

// ---------------------------------------------------------------------------
// Prep 1: per-batch softmax of action logits -> g_mask
// ---------------------------------------------------------------------------
__global__ void prep_mask_kernel(const float* __restrict__ act){
    int b = blockIdx.x * blockDim.x + threadIdx.x;
    if (b < 64){
        float v[9];
        float mx = -3.4e38f;
        #pragma unroll
        for (int t = 0; t < 9; t++){ v[t] = act[b*9 + t]; mx = fmaxf(mx, v[t]); }
        float s = 0.f;
        #pragma unroll
        for (int t = 0; t < 9; t++){ v[t] = expf(v[t] - mx); s += v[t]; }
        float inv = 1.f / s;
        #pragma unroll
        for (int t = 0; t < 9; t++) g_mask[b*9 + t] = v[t] * inv;
    }
}

// ---------------------------------------------------------------------------
// Prep 2: W[o][i][ky][kx] -> g_W2[t][i][o], rounded to tf32 (RNA)
// ---------------------------------------------------------------------------
__global__ void prep_w_kernel(const float* __restrict__ w){
    int idx = blockIdx.x * blockDim.x + threadIdx.x;
    if (idx < 9*256*256){
        int t = idx % 9;
        int r = idx / 9;
        int i = r & 255;
        int o = r >> 8;
        unsigned v;
        asm("cvt.rna.tf32.f32 %0, %1;" : "=r"(v) : "f"(w[idx]));
        reinterpret_cast<unsigned*>(g_W2)[(t*256 + i)*256 + o] = v;
    }
}

// ---------------------------------------------------------------------------
// Main: implicit-GEMM conv, TF32 mma.sync m16n8k8, cp.async 2-stage pipeline.
// Grid: (N tiles = 32, M tiles = 2, batch = 64), 256 threads (8 warps, 2x4).
// K ordering: k = t*256 + i  ->  each 32-wide K-tile has a single tap t, so the
// softmax mask is a scalar per K-tile, folded into the B fragment (with RNA
// tf32 rounding of the exact product m_t * x).
// ---------------------------------------------------------------------------
__global__ void __launch_bounds__(256, 2) masc_conv_kernel(
    const float* __restrict__ inp, float* __restrict__ out)
{
    extern __shared__ float smem[];
    __shared__ float s_mask[9];

    const int tid  = threadIdx.x;
    const int b    = blockIdx.z;
    const int m0   = blockIdx.y * BM;
    const int p0   = blockIdx.x * BN;
    const int lane = tid & 31;
    const int wid  = tid >> 5;
    const int wm   = (wid >> 2) * 64;   // warp M offset (2 warps in M)
    const int wn   = (wid & 3)  * 32;   // warp N offset (4 warps in N)
    const int g    = lane >> 2;         // groupID
    const int tig  = lane & 3;          // threadID_in_group

    if (tid < 9) s_mask[tid] = g_mask[b*9 + tid];
    const float* inpB = inp + (size_t)b * CC * HWP;

    float acc[4][4][4];
    #pragma unroll
    for (int mi = 0; mi < 4; mi++)
        #pragma unroll
        for (int ni = 0; ni < 4; ni++)
            #pragma unroll
            for (int r = 0; r < 4; r++) acc[mi][ni][r] = 0.f;

    // -------- stage: async-copy one K-tile (A from g_W2, B im2col from inp) --
    auto stage = [&](int kt, int s){
        float* sA = smem + s * STAGE_F;
        float* sB = sA + BK * LDA;
        const int t  = kt >> 3;
        const int i0 = (kt & 7) << 5;

        // A tile: [BK][BM], rows contiguous in g_W2 -> 16B vector cp.async
        #pragma unroll
        for (int ss = 0; ss < 4; ss++){
            int j   = tid + 256*ss;          // float4 index in [0,1024)
            int row = j >> 5;                // k row 0..31
            int c4  = j & 31;                // float4 col 0..31
            const float* src = g_W2 + ((t*256 + i0 + row)*256 + m0 + c4*4);
            unsigned dst = smem_u32(sA + row*LDA + c4*4);
            asm volatile("cp.async.cg.shared.global [%0], [%1], 16;\n"
                         :: "r"(dst), "l"(src));
        }

        // B tile: [BK][BN] shifted pixels of tap t, scalar cp.async w/ zfill
        const int dy = t/3 - 1, dx = t%3 - 1;
        #pragma unroll
        for (int ss = 0; ss < 16; ss++){
            int j  = tid + 256*ss;           // elem index in [0,4096)
            int kl = j >> 7;                 // k row 0..31
            int n  = j & 127;                // pixel within tile
            int p  = p0 + n;
            int y  = (p >> 6) + dy;
            int x  = (p & 63) + dx;
            bool valid = ((unsigned)y < 64u) & ((unsigned)x < 64u);
            const float* src = inpB + (((i0 + kl) << 12) + (y << 6) + x);
            if (!valid) src = inpB;          // keep address sane; zero-filled
            unsigned dst = smem_u32(sB + kl*LDA + n);
            int sz = valid ? 4 : 0;
            asm volatile("cp.async.ca.shared.global [%0], [%1], 4, %2;\n"
                         :: "r"(dst), "l"(src), "r"(sz));
        }
        asm volatile("cp.async.commit_group;\n");
    };

    stage(0, 0);

    for (int kt = 0; kt < NKT; kt++){
        if (kt + 1 < NKT){
            stage(kt + 1, (kt + 1) & 1);
            asm volatile("cp.async.wait_group 1;\n");
        } else {
            asm volatile("cp.async.wait_group 0;\n");
        }
        __syncthreads();

        const float mt = s_mask[kt >> 3];
        const float*    sA  = smem + (kt & 1) * STAGE_F;
        const float*    sB  = sA + BK * LDA;
        const unsigned* sAu = reinterpret_cast<const unsigned*>(sA);

        #pragma unroll
        for (int ks = 0; ks < 4; ks++){
            const int ko = ks * 8;

            // A fragments (already tf32 in smem): a0(g,tig) a1(g+8,tig)
            //                                     a2(g,tig+4) a3(g+8,tig+4)
            unsigned afr[4][4];
            #pragma unroll
            for (int mi = 0; mi < 4; mi++){
                int m = wm + mi*16 + g;
                afr[mi][0] = sAu[(ko+tig  )*LDA + m];
                afr[mi][1] = sAu[(ko+tig  )*LDA + m + 8];
                afr[mi][2] = sAu[(ko+tig+4)*LDA + m];
                afr[mi][3] = sAu[(ko+tig+4)*LDA + m + 8];
            }
            // B fragments: scale by mask, round exact product to tf32 (RNA)
            unsigned bfr[4][2];
            #pragma unroll
            for (int ni = 0; ni < 4; ni++){
                int n = wn + ni*8 + g;
                float f0 = sB[(ko+tig  )*LDA + n] * mt;
                float f1 = sB[(ko+tig+4)*LDA + n] * mt;
                asm("cvt.rna.tf32.f32 %0, %1;" : "=r"(bfr[ni][0]) : "f"(f0));
                asm("cvt.rna.tf32.f32 %0, %1;" : "=r"(bfr[ni][1]) : "f"(f1));
            }
            #pragma unroll
            for (int mi = 0; mi < 4; mi++)
                #pragma unroll
                for (int ni = 0; ni < 4; ni++){
                    asm volatile(
                        "mma.sync.aligned.m16n8k8.row.col.f32.tf32.tf32.f32 "
                        "{%0,%1,%2,%3}, {%4,%5,%6,%7}, {%8,%9}, {%0,%1,%2,%3};\n"
                        : "+f"(acc[mi][ni][0]), "+f"(acc[mi][ni][1]),
                          "+f"(acc[mi][ni][2]), "+f"(acc[mi][ni][3])
                        : "r"(afr[mi][0]), "r"(afr[mi][1]),
                          "r"(afr[mi][2]), "r"(afr[mi][3]),
                          "r"(bfr[ni][0]), "r"(bfr[ni][1]));
                }
        }
        __syncthreads();
    }

    // -------- epilogue: c0/c1 and c2/c3 are adjacent columns -> 8B stores ---
    float* outB = out + ((size_t)(b*CC + m0 + wm)) * HWP + p0 + wn;
    #pragma unroll
    for (int mi = 0; mi < 4; mi++){
        #pragma unroll
        for (int ni = 0; ni < 4; ni++){
            int r0  = mi*16 + g;
            int col = ni*8 + 2*tig;
            float2 v0 = make_float2(acc[mi][ni][0], acc[mi][ni][1]);
            float2 v1 = make_float2(acc[mi][ni][2], acc[mi][ni][3]);
            *reinterpret_cast<float2*>(outB + (size_t)r0      * HWP + col) = v0;
            *reinterpret_cast<float2*>(outB + (size_t)(r0 + 8)* HWP + col) = v1;
        }
    }
}

// ---------------------------------------------------------------------------
extern "C" void kernel_launch(void* const* d_in, const int* in_sizes, int n_in,
                              void* d_out, int out_size)
{
    const float* inp = (const float*)d_in[0];   // [64,256,64,64] f32
    const float* act = (const float*)d_in[1];   // [64,9] f32
    const float* w   = (const float*)d_in[2];   // [256,256,3,3] f32
    float* out = (float*)d_out;                 // [64,256,64,64] f32

    cudaFuncSetAttribute(masc_conv_kernel,
                         cudaFuncAttributeMaxDynamicSharedMemorySize, SMEM_BYTES);

    prep_mask_kernel<<<2, 32>>>(act);
    prep_w_kernel<<<1152, 512>>>(w);            // 589824 threads exactly
    masc_conv_kernel<<<dim3(32, 2, 64), 256, SMEM_BYTES>>>(inp, out);

    (void)in_sizes; (void)n_in; (void)out_size;
}

// round 10
// speedup vs baseline: 1.5632x; 1.5632x over previous
#include <cuda_runtime.h>
#include <cstdint>

// ---------------------------------------------------------------------------
// out[b,o,y,x] = sum_{t,i} softmax(a_b)[t] * W[o,i,t] * X[b,i,y+dy,x+dx]
// Implicit GEMM per batch: M=256 (one CTA), N=4096 pixels (32 tiles of 128),
// K=2304 = 9 taps x 256 ch, K-tile 32.  mma.sync.m16n8k8 TF32.
// A: pre-fragmented tf32 W in gmem (2.36MB, L2-resident) -> 16B cp.async.
// B: NHWC fp32 input -> 16B cp.async into XOR-swizzled [n][k] smem; mask
//    folded at fragment time (single rounding of m_t * x).
// 3-stage cp.async ring, ONE __syncthreads per K-iteration.
// ---------------------------------------------------------------------------

#define BM   256
#define BN   128
#define BK   32
#define NKT  72
#define NST  3
#define A_BYTES 32768                 // 2048 uint4: [widm4][mi4][ks4][lane32]
#define B_BYTES 16384                 // 128 rows x 128 B (32 tf32), XOR swizzle
#define STAGE_BYTES (A_BYTES + B_BYTES)
#define HDR  128
#define SMEM_TOTAL (HDR + NST*STAGE_BYTES)   // 147584 B

// Scratch (__device__ globals: allocation-free rule)
__device__ float g_Wf[NKT*8192];            // prefragged tf32 W, 2.36 MB
__device__ float g_Xt[64ull*4096*256];      // NHWC raw fp32, 256 MB
__device__ float g_mask[64*9];

__device__ __forceinline__ unsigned smem_u32(const void* p){
    return (unsigned)__cvta_generic_to_shared(p);
}

// ---------------------------------------------------------------------------
__global__ void prep_mask_kernel(const float* __restrict__ act){
    int b = blockIdx.x * blockDim.x + threadIdx.x;
    if (b < 64){
        float v[9]; float mx = -3.4e38f;
        #pragma unroll
        for (int t = 0; t < 9; t++){ v[t] = act[b*9+t]; mx = fmaxf(mx, v[t]); }
        float s = 0.f;
        #pragma unroll
        for (int t = 0; t < 9; t++){ v[t] = expf(v[t]-mx); s += v[t]; }
        float inv = 1.f/s;
        #pragma unroll
        for (int t = 0; t < 9; t++) g_mask[b*9+t] = v[t]*inv;
    }
}

// W[o][i][t] -> fragment-order tf32: uint4 per (kt, widm, mi, ks, lane) =
// { A(k0,m), A(k0,m+8), A(k0+4,m), A(k0+4,m+8) },  A(k,m)=tf32(W[m][i(k)][t])
__global__ void prep_wf_kernel(const float* __restrict__ w){
    int idx = blockIdx.x * blockDim.x + threadIdx.x;     // 147456 uint4
    if (idx >= NKT*2048) return;
    int lane =  idx        & 31;
    int ks   = (idx >> 5)  & 3;
    int mi   = (idx >> 7)  & 3;
    int widm = (idx >> 9)  & 3;
    int kt   =  idx >> 11;
    int g = lane >> 2, tig = lane & 3;
    int m  = widm*64 + mi*16 + g;
    int t  = kt >> 3;
    int i0 = (kt & 7) * 32;
    int ia = i0 + ks*8 + tig;
    int ib = ia + 4;
    float w0 = w[(size_t)m    *2304 + ia*9 + t];
    float w1 = w[(size_t)(m+8)*2304 + ia*9 + t];
    float w2 = w[(size_t)m    *2304 + ib*9 + t];
    float w3 = w[(size_t)(m+8)*2304 + ib*9 + t];
    unsigned u0,u1,u2,u3;
    asm("cvt.rna.tf32.f32 %0, %1;" : "=r"(u0) : "f"(w0));
    asm("cvt.rna.tf32.f32 %0, %1;" : "=r"(u1) : "f"(w1));
    asm("cvt.rna.tf32.f32 %0, %1;" : "=r"(u2) : "f"(w2));
    asm("cvt.rna.tf32.f32 %0, %1;" : "=r"(u3) : "f"(w3));
    reinterpret_cast<uint4*>(g_Wf)[idx] = make_uint4(u0,u1,u2,u3);
}

// X[b][c][p] -> g_Xt[b][p][c] (raw fp32), 32x32 smem transpose
__global__ void prep_x_kernel(const float* __restrict__ inp){
    __shared__ float tile[32][33];
    int b = blockIdx.z, p0 = blockIdx.x*32, c0 = blockIdx.y*32;
    int tx = threadIdx.x, ty = threadIdx.y;              // (32, 8)
    const float* src = inp + (((size_t)b*256 + c0)*4096 + p0);
    #pragma unroll
    for (int r = 0; r < 4; r++)
        tile[ty + 8*r][tx] = src[(size_t)(ty + 8*r)*4096 + tx];
    __syncthreads();
    float* dst = g_Xt + (((size_t)b*4096 + p0)*256 + c0);
    #pragma unroll
    for (int r = 0; r < 4; r++)
        dst[(size_t)(ty + 8*r)*256 + tx] = tile[tx][ty + 8*r];
}

// ---------------------------------------------------------------------------
__global__ void __launch_bounds__(256, 1) masc_conv_kernel(float* __restrict__ out)
{
    extern __shared__ char smem[];
    const unsigned sb = smem_u32(smem);
    const int tid  = threadIdx.x;
    const int lane = tid & 31;
    const int wid  = tid >> 5;
    const int widm = wid >> 1;          // 4 warps in M
    const int wn   = (wid & 1) * 64;    // 2 warps in N
    const int g    = lane >> 2;
    const int tig  = lane & 3;
    const int b    = blockIdx.z;
    const int p0   = blockIdx.x * BN;

    float* s_mask = reinterpret_cast<float*>(smem);
    if (tid < 9) s_mask[tid] = g_mask[b*9 + tid];
    const float* xB = g_Xt + (size_t)b*4096*256;

    // B staging role: thread handles row n (pixel), 4 of 8 16B segments
    const int bn   = tid & 127;
    const int bs0  = (tid >> 7) * 4;

    float acc[4][8][4];
    #pragma unroll
    for (int mi = 0; mi < 4; mi++)
        #pragma unroll
        for (int ni = 0; ni < 8; ni++)
            #pragma unroll
            for (int r = 0; r < 4; r++) acc[mi][ni][r] = 0.f;

    // ---- stage one K-tile into slot s ----
    auto stage = [&](int kt, int s){
        const unsigned stg = sb + HDR + s*STAGE_BYTES;
        // A: 2048 uint4, already in smem order in g_Wf
        const uint4* srcA = reinterpret_cast<const uint4*>(g_Wf) + kt*2048;
        #pragma unroll
        for (int q = 0; q < 8; q++){
            int j = tid + 256*q;
            asm volatile("cp.async.cg.shared.global [%0], [%1], 16;\n"
                         :: "r"(stg + j*16), "l"(srcA + j));
        }
        // B: 128 rows x 8 segs of 16B, XOR-swizzled quads, zfill out-of-range
        const int t  = kt >> 3;
        const int i0 = (kt & 7) * 32;
        const int dy = t/3 - 1, dx = t%3 - 1;
        const int p  = p0 + bn;
        const int y  = (p >> 6) + dy;
        const int x  = (p & 63) + dx;
        const bool valid = ((unsigned)y < 64u) & ((unsigned)x < 64u);
        const float* srow = xB + ((size_t)(valid ? (y*64 + x) : 0)*256 + i0);
        const int sz = valid ? 16 : 0;
        const unsigned rowDst = stg + A_BYTES + bn*128;
        #pragma unroll
        for (int q = 0; q < 4; q++){
            int sgi = bs0 + q;
            unsigned dst = rowDst + ((sgi ^ (bn & 7)) * 16);
            asm volatile("cp.async.cg.shared.global [%0], [%1], 16, %2;\n"
                         :: "r"(dst), "l"(srow + sgi*4), "r"(sz));
        }
        asm volatile("cp.async.commit_group;\n");
    };

    // ---- prologue ----
    stage(0, 0);
    stage(1, 1);

    // ---- main loop: one __syncthreads per iteration ----
    #pragma unroll 1
    for (int kt = 0; kt < NKT; kt++){
        if (kt < NKT-1) asm volatile("cp.async.wait_group 1;\n");
        else            asm volatile("cp.async.wait_group 0;\n");
        __syncthreads();

        const float mt = s_mask[kt >> 3];
        const char* stg = smem + HDR + (kt % 3)*STAGE_BYTES;
        const uint4* sA = reinterpret_cast<const uint4*>(stg);
        const char*  sB = stg + A_BYTES;

        #pragma unroll
        for (int ks = 0; ks < 4; ks++){
            uint4 af[4];
            #pragma unroll
            for (int mi = 0; mi < 4; mi++)
                af[mi] = sA[((widm*4 + mi)*4 + ks)*32 + lane];

            unsigned bf[8][2];
            #pragma unroll
            for (int ni = 0; ni < 8; ni++){
                int n = wn + ni*8 + g;
                unsigned q0 = ( (2*ks)   ^ (n & 7) ) * 16 + tig*4;
                unsigned q1 = ( (2*ks+1) ^ (n & 7) ) * 16 + tig*4;
                float x0 = *reinterpret_cast<const float*>(sB + n*128 + q0) * mt;
                float x1 = *reinterpret_cast<const float*>(sB + n*128 + q1) * mt;
                asm("cvt.rna.tf32.f32 %0, %1;" : "=r"(bf[ni][0]) : "f"(x0));
                asm("cvt.rna.tf32.f32 %0, %1;" : "=r"(bf[ni][1]) : "f"(x1));
            }
            #pragma unroll
            for (int mi = 0; mi < 4; mi++)
                #pragma unroll
                for (int ni = 0; ni < 8; ni++){
                    asm volatile(
                        "mma.sync.aligned.m16n8k8.row.col.f32.tf32.tf32.f32 "
                        "{%0,%1,%2,%3}, {%4,%5,%6,%7}, {%8,%9}, {%0,%1,%2,%3};\n"
                        : "+f"(acc[mi][ni][0]), "+f"(acc[mi][ni][1]),
                          "+f"(acc[mi][ni][2]), "+f"(acc[mi][ni][3])
                        : "r"(af[mi].x), "r"(af[mi].y),
                          "r"(af[mi].z), "r"(af[mi].w),
                          "r"(bf[ni][0]), "r"(bf[ni][1]));
                }
        }

        if (kt + 2 < NKT) stage(kt + 2, (kt + 2) % 3);
    }

    // ---- epilogue: c0/c1 and c2/c3 are adjacent columns -> 8B stores ----
    float* outB = out + ((size_t)(b*256 + widm*64))*4096 + p0 + wn;
    #pragma unroll
    for (int mi = 0; mi < 4; mi++){
        #pragma unroll
        for (int ni = 0; ni < 8; ni++){
            int r0  = mi*16 + g;
            int col = ni*8 + 2*tig;
            float2 v0 = make_float2(acc[mi][ni][0], acc[mi][ni][1]);
            float2 v1 = make_float2(acc[mi][ni][2], acc[mi][ni][3]);
            *reinterpret_cast<float2*>(outB + (size_t)r0      *4096 + col) = v0;
            *reinterpret_cast<float2*>(outB + (size_t)(r0 + 8)*4096 + col) = v1;
        }
    }
}

// ---------------------------------------------------------------------------
extern "C" void kernel_launch(void* const* d_in, const int* in_sizes, int n_in,
                              void* d_out, int out_size)
{
    const float* inp = (const float*)d_in[0];   // [64,256,64,64] f32
    const float* act = (const float*)d_in[1];   // [64,9] f32
    const float* w   = (const float*)d_in[2];   // [256,256,3,3] f32
    float* out = (float*)d_out;

    cudaFuncSetAttribute(masc_conv_kernel,
                         cudaFuncAttributeMaxDynamicSharedMemorySize, SMEM_TOTAL);

    prep_mask_kernel<<<2, 32>>>(act);
    prep_wf_kernel<<<576, 256>>>(w);            // 147456 uint4
    prep_x_kernel<<<dim3(128, 8, 64), dim3(32, 8)>>>(inp);
    masc_conv_kernel<<<dim3(32, 1, 64), 256, SMEM_TOTAL>>>(out);

    (void)in_sizes; (void)n_in; (void)out_size;
}

// round 11
// speedup vs baseline: 1.6272x; 1.0409x over previous
#include <cuda_runtime.h>
#include <cstdint>

// ---------------------------------------------------------------------------
// out[b,o,y,x] = sum_{t,i} softmax(a_b)[t] * W[o,i,t] * X[b,i,y+dy,x+dx]
// Implicit GEMM per batch: M=256 (one CTA), N=4096 pixels (32 tiles of 128),
// K=2304 = 9 taps x 256 ch, K-tile 32.  mma.sync.m16n8k8 TF32.
// A: PER-BATCH mask-scaled prefragged tf32 W in gmem (151 MB) -> 16B cp.async;
//    mainloop A path = LDS.128 -> HMMA, no math.
// B: NHWC tf32-rounded input -> 16B cp.async into XOR-swizzled [n][k] smem;
//    mainloop B path = LDS.32 -> HMMA, no math.
// 4-stage cp.async ring, ONE __syncthreads per K-iteration, staging issued
// before the MMA block so copies overlap compute.
// ---------------------------------------------------------------------------

#define BM   256
#define BN   128
#define BK   32
#define NKT  72
#define NST  4
#define A_BYTES 32768                 // 2048 uint4: [widm4][mi4][ks4][lane32]
#define B_BYTES 16384                 // 128 rows x 128 B (32 tf32), XOR swizzle
#define STAGE_BYTES (A_BYTES + B_BYTES)
#define HDR  128
#define SMEM_TOTAL (HDR + NST*STAGE_BYTES)   // 196736 B

// Scratch (__device__ globals: allocation-free rule)
__device__ float g_Wf[NKT*8192];            // prefragged RAW fp32 W, 2.36 MB
__device__ float g_WfB[64ull*NKT*8192];     // per-batch masked tf32 frags, 151 MB
__device__ float g_Xt[64ull*4096*256];      // NHWC tf32-rounded, 256 MB
__device__ float g_mask[64*9];

__device__ __forceinline__ unsigned smem_u32(const void* p){
    return (unsigned)__cvta_generic_to_shared(p);
}

// ---------------------------------------------------------------------------
__global__ void prep_mask_kernel(const float* __restrict__ act){
    int b = blockIdx.x * blockDim.x + threadIdx.x;
    if (b < 64){
        float v[9]; float mx = -3.4e38f;
        #pragma unroll
        for (int t = 0; t < 9; t++){ v[t] = act[b*9+t]; mx = fmaxf(mx, v[t]); }
        float s = 0.f;
        #pragma unroll
        for (int t = 0; t < 9; t++){ v[t] = expf(v[t]-mx); s += v[t]; }
        float inv = 1.f/s;
        #pragma unroll
        for (int t = 0; t < 9; t++) g_mask[b*9+t] = v[t]*inv;
    }
}

// W[o][i][t] -> fragment-order RAW fp32: uint4 per (kt, widm, mi, ks, lane) =
// { A(k0,m), A(k0,m+8), A(k0+4,m), A(k0+4,m+8) },  A(k,m)=W[m][i(k)][t]
__global__ void prep_wf_kernel(const float* __restrict__ w){
    int idx = blockIdx.x * blockDim.x + threadIdx.x;     // 147456 float4
    if (idx >= NKT*2048) return;
    int lane =  idx        & 31;
    int ks   = (idx >> 5)  & 3;
    int mi   = (idx >> 7)  & 3;
    int widm = (idx >> 9)  & 3;
    int kt   =  idx >> 11;
    int g = lane >> 2, tig = lane & 3;
    int m  = widm*64 + mi*16 + g;
    int t  = kt >> 3;
    int i0 = (kt & 7) * 32;
    int ia = i0 + ks*8 + tig;
    int ib = ia + 4;
    float4 v;
    v.x = w[(size_t)m    *2304 + ia*9 + t];
    v.y = w[(size_t)(m+8)*2304 + ia*9 + t];
    v.z = w[(size_t)m    *2304 + ib*9 + t];
    v.w = w[(size_t)(m+8)*2304 + ib*9 + t];
    reinterpret_cast<float4*>(g_Wf)[idx] = v;
}

// g_Wf (raw) x mask[b][t] -> g_WfB[b], tf32-rounded (single rounding of m*w)
__global__ void prep_wfb_kernel(){
    int idx = blockIdx.x * blockDim.x + threadIdx.x;     // 0..147455
    int b   = blockIdx.y;
    int t   = idx >> 14;                                 // (idx>>11)>>3
    float mt = g_mask[b*9 + t];
    float4 v = reinterpret_cast<const float4*>(g_Wf)[idx];
    unsigned u0,u1,u2,u3;
    asm("cvt.rna.tf32.f32 %0, %1;" : "=r"(u0) : "f"(v.x*mt));
    asm("cvt.rna.tf32.f32 %0, %1;" : "=r"(u1) : "f"(v.y*mt));
    asm("cvt.rna.tf32.f32 %0, %1;" : "=r"(u2) : "f"(v.z*mt));
    asm("cvt.rna.tf32.f32 %0, %1;" : "=r"(u3) : "f"(v.w*mt));
    reinterpret_cast<uint4*>(g_WfB)[(size_t)b*(NKT*2048) + idx] =
        make_uint4(u0,u1,u2,u3);
}

// X[b][c][p] -> g_Xt[b][p][c], tf32-rounded.  32x32 smem transpose.
__global__ void prep_x_kernel(const float* __restrict__ inp){
    __shared__ float tile[32][33];
    int b = blockIdx.z, p0 = blockIdx.x*32, c0 = blockIdx.y*32;
    int tx = threadIdx.x, ty = threadIdx.y;              // (32, 8)
    const float* src = inp + (((size_t)b*256 + c0)*4096 + p0);
    #pragma unroll
    for (int r = 0; r < 4; r++)
        tile[ty + 8*r][tx] = src[(size_t)(ty + 8*r)*4096 + tx];
    __syncthreads();
    unsigned* dst = reinterpret_cast<unsigned*>(g_Xt) + (((size_t)b*4096 + p0)*256 + c0);
    #pragma unroll
    for (int r = 0; r < 4; r++){
        unsigned u;
        asm("cvt.rna.tf32.f32 %0, %1;" : "=r"(u) : "f"(tile[tx][ty + 8*r]));
        dst[(size_t)(ty + 8*r)*256 + tx] = u;
    }
}

// ---------------------------------------------------------------------------
__global__ void __launch_bounds__(256, 1) masc_conv_kernel(float* __restrict__ out)
{
    extern __shared__ char smem[];
    const unsigned sb = smem_u32(smem);
    const int tid  = threadIdx.x;
    const int lane = tid & 31;
    const int wid  = tid >> 5;
    const int widm = wid >> 1;          // 4 warps in M
    const int wn   = (wid & 1) * 64;    // 2 warps in N
    const int g    = lane >> 2;
    const int tig  = lane & 3;
    const int b    = blockIdx.z;
    const int p0   = blockIdx.x * BN;

    const float* xB = g_Xt + (size_t)b*4096*256;
    const uint4* aB = reinterpret_cast<const uint4*>(g_WfB) + (size_t)b*(NKT*2048);

    // B staging role: thread handles row n (pixel), 4 of 8 16B segments
    const int bn   = tid & 127;
    const int bs0  = (tid >> 7) * 4;

    float acc[4][8][4];
    #pragma unroll
    for (int mi = 0; mi < 4; mi++)
        #pragma unroll
        for (int ni = 0; ni < 8; ni++)
            #pragma unroll
            for (int r = 0; r < 4; r++) acc[mi][ni][r] = 0.f;

    // ---- stage one K-tile into slot s ----
    auto stage = [&](int kt, int s){
        const unsigned stg = sb + HDR + s*STAGE_BYTES;
        // A: 2048 uint4, already in smem fragment order (mask pre-applied)
        const uint4* srcA = aB + kt*2048;
        #pragma unroll
        for (int q = 0; q < 8; q++){
            int j = tid + 256*q;
            asm volatile("cp.async.cg.shared.global [%0], [%1], 16;\n"
                         :: "r"(stg + j*16), "l"(srcA + j));
        }
        // B: 128 rows x 8 segs of 16B, XOR-swizzled quads, zfill out-of-range
        const int t  = kt >> 3;
        const int i0 = (kt & 7) * 32;
        const int dy = t/3 - 1, dx = t%3 - 1;
        const int p  = p0 + bn;
        const int y  = (p >> 6) + dy;
        const int x  = (p & 63) + dx;
        const bool valid = ((unsigned)y < 64u) & ((unsigned)x < 64u);
        const float* srow = xB + ((size_t)(valid ? (y*64 + x) : 0)*256 + i0);
        const int sz = valid ? 16 : 0;
        const unsigned rowDst = stg + A_BYTES + bn*128;
        #pragma unroll
        for (int q = 0; q < 4; q++){
            int sgi = bs0 + q;
            unsigned dst = rowDst + ((sgi ^ (bn & 7)) * 16);
            asm volatile("cp.async.cg.shared.global [%0], [%1], 16, %2;\n"
                         :: "r"(dst), "l"(srow + sgi*4), "r"(sz));
        }
        asm volatile("cp.async.commit_group;\n");
    };

    // ---- prologue: fill 3 of 4 slots ----
    stage(0, 0);
    stage(1, 1);
    stage(2, 2);

    // ---- main loop: one __syncthreads per iteration ----
    #pragma unroll 1
    for (int kt = 0; kt < NKT; kt++){
        if (kt < NKT-2)      asm volatile("cp.async.wait_group 2;\n");
        else if (kt < NKT-1) asm volatile("cp.async.wait_group 1;\n");
        else                 asm volatile("cp.async.wait_group 0;\n");
        __syncthreads();

        // issue next stage FIRST so the copies overlap the MMA block
        if (kt + 3 < NKT) stage(kt + 3, (kt + 3) & 3);

        const char* stg = smem + HDR + (kt & 3)*STAGE_BYTES;
        const uint4* sA = reinterpret_cast<const uint4*>(stg);
        const char*  sB = stg + A_BYTES;

        #pragma unroll
        for (int ks = 0; ks < 4; ks++){
            uint4 af[4];
            #pragma unroll
            for (int mi = 0; mi < 4; mi++)
                af[mi] = sA[((widm*4 + mi)*4 + ks)*32 + lane];

            unsigned bf[8][2];
            #pragma unroll
            for (int ni = 0; ni < 8; ni++){
                int n = wn + ni*8 + g;
                unsigned q0 = ( (2*ks)   ^ (n & 7) ) * 16 + tig*4;
                unsigned q1 = ( (2*ks+1) ^ (n & 7) ) * 16 + tig*4;
                bf[ni][0] = *reinterpret_cast<const unsigned*>(sB + n*128 + q0);
                bf[ni][1] = *reinterpret_cast<const unsigned*>(sB + n*128 + q1);
            }
            #pragma unroll
            for (int mi = 0; mi < 4; mi++)
                #pragma unroll
                for (int ni = 0; ni < 8; ni++){
                    asm volatile(
                        "mma.sync.aligned.m16n8k8.row.col.f32.tf32.tf32.f32 "
                        "{%0,%1,%2,%3}, {%4,%5,%6,%7}, {%8,%9}, {%0,%1,%2,%3};\n"
                        : "+f"(acc[mi][ni][0]), "+f"(acc[mi][ni][1]),
                          "+f"(acc[mi][ni][2]), "+f"(acc[mi][ni][3])
                        : "r"(af[mi].x), "r"(af[mi].y),
                          "r"(af[mi].z), "r"(af[mi].w),
                          "r"(bf[ni][0]), "r"(bf[ni][1]));
                }
        }
    }

    // ---- epilogue: c0/c1 and c2/c3 are adjacent columns -> 8B stores ----
    float* outB = out + ((size_t)(b*256 + widm*64))*4096 + p0 + wn;
    #pragma unroll
    for (int mi = 0; mi < 4; mi++){
        #pragma unroll
        for (int ni = 0; ni < 8; ni++){
            int r0  = mi*16 + g;
            int col = ni*8 + 2*tig;
            float2 v0 = make_float2(acc[mi][ni][0], acc[mi][ni][1]);
            float2 v1 = make_float2(acc[mi][ni][2], acc[mi][ni][3]);
            *reinterpret_cast<float2*>(outB + (size_t)r0      *4096 + col) = v0;
            *reinterpret_cast<float2*>(outB + (size_t)(r0 + 8)*4096 + col) = v1;
        }
    }
}

// ---------------------------------------------------------------------------
extern "C" void kernel_launch(void* const* d_in, const int* in_sizes, int n_in,
                              void* d_out, int out_size)
{
    const float* inp = (const float*)d_in[0];   // [64,256,64,64] f32
    const float* act = (const float*)d_in[1];   // [64,9] f32
    const float* w   = (const float*)d_in[2];   // [256,256,3,3] f32
    float* out = (float*)d_out;

    cudaFuncSetAttribute(masc_conv_kernel,
                         cudaFuncAttributeMaxDynamicSharedMemorySize, SMEM_TOTAL);

    prep_mask_kernel<<<2, 32>>>(act);
    prep_wf_kernel<<<576, 256>>>(w);                    // 147456 float4
    prep_wfb_kernel<<<dim3(576, 64), 256>>>();          // 151 MB masked frags
    prep_x_kernel<<<dim3(128, 8, 64), dim3(32, 8)>>>(inp);
    masc_conv_kernel<<<dim3(32, 1, 64), 256, SMEM_TOTAL>>>(out);

    (void)in_sizes; (void)n_in; (void)out_size;
}

// round 12
// speedup vs baseline: 1.6489x; 1.0134x over previous
#include <cuda_runtime.h>
#include <cstdint>

// ---------------------------------------------------------------------------
// out[b,o,y,x] = sum_{t,i} softmax(a_b)[t] * W[o,i,t] * X[b,i,y+dy,x+dx]
// Implicit GEMM per batch: M=256 (one CTA), N=4096 pixels (32 tiles of 128),
// K=2304 = 9 taps x 256 ch, K-tile 32.  mma.sync.m16n8k8 TF32.
// A: per-batch mask-scaled prefragged tf32 W (151 MB gmem) -> 16B cp.async;
//    compute = LDS.128 only.
// B: NHWC tf32 input with PERMUTED channel order within each 32-ch group so
//    each thread's 8 B-frag values per n-tile are 32 contiguous bytes ->
//    2x LDS.128 per n-tile (was 8x LDS.32).  XOR-quad swizzle keeps both the
//    16B cp.async staging and the LDS.128 reads bank-conflict-free.
// Mainloop interleaves B prefetch with MMA at ni granularity to overlap the
// smem crossbar with the tensor pipe (they were serialized by phase-locking).
// ---------------------------------------------------------------------------

#define BM   256
#define BN   128
#define BK   32
#define NKT  72
#define NST  4
#define A_BYTES 32768                 // 2048 uint4: [widm4][mi4][ks4][lane32]
#define B_BYTES 16384                 // 128 rows x 128 B, permuted-k + XOR quads
#define STAGE_BYTES (A_BYTES + B_BYTES)
#define HDR  128
#define SMEM_TOTAL (HDR + NST*STAGE_BYTES)   // 196736 B

// Scratch (__device__ globals: allocation-free rule)
__device__ float g_Wf[NKT*8192];            // prefragged RAW fp32 W, 2.36 MB
__device__ float g_WfB[64ull*NKT*8192];     // per-batch masked tf32 frags, 151 MB
__device__ float g_Xt[64ull*4096*256];      // NHWC tf32, permuted-k, 256 MB
__device__ float g_mask[64*9];

__device__ __forceinline__ unsigned smem_u32(const void* p){
    return (unsigned)__cvta_generic_to_shared(p);
}

// ---------------------------------------------------------------------------
__global__ void prep_mask_kernel(const float* __restrict__ act){
    int b = blockIdx.x * blockDim.x + threadIdx.x;
    if (b < 64){
        float v[9]; float mx = -3.4e38f;
        #pragma unroll
        for (int t = 0; t < 9; t++){ v[t] = act[b*9+t]; mx = fmaxf(mx, v[t]); }
        float s = 0.f;
        #pragma unroll
        for (int t = 0; t < 9; t++){ v[t] = expf(v[t]-mx); s += v[t]; }
        float inv = 1.f/s;
        #pragma unroll
        for (int t = 0; t < 9; t++) g_mask[b*9+t] = v[t]*inv;
    }
}

// W[o][i][t] -> fragment-order RAW fp32 (see R10 comment)
__global__ void prep_wf_kernel(const float* __restrict__ w){
    int idx = blockIdx.x * blockDim.x + threadIdx.x;     // 147456 float4
    if (idx >= NKT*2048) return;
    int lane =  idx        & 31;
    int ks   = (idx >> 5)  & 3;
    int mi   = (idx >> 7)  & 3;
    int widm = (idx >> 9)  & 3;
    int kt   =  idx >> 11;
    int g = lane >> 2, tig = lane & 3;
    int m  = widm*64 + mi*16 + g;
    int t  = kt >> 3;
    int i0 = (kt & 7) * 32;
    int ia = i0 + ks*8 + tig;
    int ib = ia + 4;
    float4 v;
    v.x = w[(size_t)m    *2304 + ia*9 + t];
    v.y = w[(size_t)(m+8)*2304 + ia*9 + t];
    v.z = w[(size_t)m    *2304 + ib*9 + t];
    v.w = w[(size_t)(m+8)*2304 + ib*9 + t];
    reinterpret_cast<float4*>(g_Wf)[idx] = v;
}

// g_Wf (raw) x mask[b][t] -> g_WfB[b], tf32 (single rounding of m*w)
__global__ void prep_wfb_kernel(){
    int idx = blockIdx.x * blockDim.x + threadIdx.x;     // 0..147455
    int b   = blockIdx.y;
    int t   = idx >> 14;
    float mt = g_mask[b*9 + t];
    float4 v = reinterpret_cast<const float4*>(g_Wf)[idx];
    unsigned u0,u1,u2,u3;
    asm("cvt.rna.tf32.f32 %0, %1;" : "=r"(u0) : "f"(v.x*mt));
    asm("cvt.rna.tf32.f32 %0, %1;" : "=r"(u1) : "f"(v.y*mt));
    asm("cvt.rna.tf32.f32 %0, %1;" : "=r"(u2) : "f"(v.z*mt));
    asm("cvt.rna.tf32.f32 %0, %1;" : "=r"(u3) : "f"(v.w*mt));
    reinterpret_cast<uint4*>(g_WfB)[(size_t)b*(NKT*2048) + idx] =
        make_uint4(u0,u1,u2,u3);
}

// X[b][c][p] -> g_Xt[b][p][perm(c)], tf32.  Channel permutation within each
// 32-ch group: pos(kl) = (kl&3)*8 + ((kl>>3)&3)*2 + ((kl>>2)&1), so that a
// thread's mma B values {k = 8ks + tig + 4h} are contiguous (tig*8 + ks*2 + h).
__global__ void prep_x_kernel(const float* __restrict__ inp){
    __shared__ float tile[32][33];
    int b = blockIdx.z, p0 = blockIdx.x*32, c0 = blockIdx.y*32;
    int tx = threadIdx.x, ty = threadIdx.y;              // (32, 8)
    const float* src = inp + (((size_t)b*256 + c0)*4096 + p0);
    #pragma unroll
    for (int r = 0; r < 4; r++)
        tile[ty + 8*r][tx] = src[(size_t)(ty + 8*r)*4096 + tx];
    __syncthreads();
    int pos = (tx&3)*8 + ((tx>>3)&3)*2 + ((tx>>2)&1);
    unsigned* dst = reinterpret_cast<unsigned*>(g_Xt) + (((size_t)b*4096 + p0)*256 + c0);
    #pragma unroll
    for (int r = 0; r < 4; r++){
        unsigned u;
        asm("cvt.rna.tf32.f32 %0, %1;" : "=r"(u) : "f"(tile[tx][ty + 8*r]));
        dst[(size_t)(ty + 8*r)*256 + pos] = u;
    }
}

// ---------------------------------------------------------------------------
__global__ void __launch_bounds__(256, 1) masc_conv_kernel(float* __restrict__ out)
{
    extern __shared__ char smem[];
    const unsigned sb = smem_u32(smem);
    const int tid  = threadIdx.x;
    const int lane = tid & 31;
    const int wid  = tid >> 5;
    const int widm = wid >> 1;          // 4 warps in M
    const int wn   = (wid & 1) * 64;    // 2 warps in N
    const int g    = lane >> 2;
    const int tig  = lane & 3;
    const int b    = blockIdx.z;
    const int p0   = blockIdx.x * BN;

    const float* xB = g_Xt + (size_t)b*4096*256;
    const uint4* aB = reinterpret_cast<const uint4*>(g_WfB) + (size_t)b*(NKT*2048);

    // B staging role: thread handles row n (pixel), 4 of 8 16B segments
    const int bn   = tid & 127;
    const int bs0  = (tid >> 7) * 4;

    float acc[4][8][4];
    #pragma unroll
    for (int mi = 0; mi < 4; mi++)
        #pragma unroll
        for (int ni = 0; ni < 8; ni++)
            #pragma unroll
            for (int r = 0; r < 4; r++) acc[mi][ni][r] = 0.f;

    // ---- stage one K-tile into slot s ----
    auto stage = [&](int kt, int s){
        const unsigned stg = sb + HDR + s*STAGE_BYTES;
        const uint4* srcA = aB + kt*2048;
        #pragma unroll
        for (int q = 0; q < 8; q++){
            int j = tid + 256*q;
            asm volatile("cp.async.cg.shared.global [%0], [%1], 16;\n"
                         :: "r"(stg + j*16), "l"(srcA + j));
        }
        const int t  = kt >> 3;
        const int i0 = (kt & 7) * 32;
        const int dy = t/3 - 1, dx = t%3 - 1;
        const int p  = p0 + bn;
        const int y  = (p >> 6) + dy;
        const int x  = (p & 63) + dx;
        const bool valid = ((unsigned)y < 64u) & ((unsigned)x < 64u);
        const float* srow = xB + ((size_t)(valid ? (y*64 + x) : 0)*256 + i0);
        const int sz = valid ? 16 : 0;
        const unsigned rowDst = stg + A_BYTES + bn*128;
        #pragma unroll
        for (int q = 0; q < 4; q++){
            int sgi = bs0 + q;
            unsigned dst = rowDst + ((sgi ^ (bn & 7)) * 16);
            asm volatile("cp.async.cg.shared.global [%0], [%1], 16, %2;\n"
                         :: "r"(dst), "l"(srow + sgi*4), "r"(sz));
        }
        asm volatile("cp.async.commit_group;\n");
    };

    // ---- prologue: fill 3 of 4 slots ----
    stage(0, 0);
    stage(1, 1);
    stage(2, 2);

    // ---- main loop: one __syncthreads per iteration ----
    #pragma unroll 1
    for (int kt = 0; kt < NKT; kt++){
        if (kt < NKT-2)      asm volatile("cp.async.wait_group 2;\n");
        else if (kt < NKT-1) asm volatile("cp.async.wait_group 1;\n");
        else                 asm volatile("cp.async.wait_group 0;\n");
        __syncthreads();

        // issue next stage FIRST so copies overlap the MMA block
        if (kt + 3 < NKT) stage(kt + 3, (kt + 3) & 3);

        const char* stg = smem + HDR + (kt & 3)*STAGE_BYTES;
        const uint4* sA = reinterpret_cast<const uint4*>(stg);
        const char*  sB = stg + A_BYTES;

        // A frags: all 16 up front (LDS.128 each)
        uint4 af[4][4];
        #pragma unroll
        for (int mi = 0; mi < 4; mi++)
            #pragma unroll
            for (int ks = 0; ks < 4; ks++)
                af[mi][ks] = sA[((widm*4 + mi)*4 + ks)*32 + lane];

        // B frags: 2 LDS.128 per n-tile, ping-pong, prefetch next ni
        // quad (tig*2+q) ^ g; uint4 = {b0(ks),b1(ks),b0(ks+1),b1(ks+1)}
        const unsigned qa0 = ((2*tig    ) ^ g) * 16;
        const unsigned qa1 = ((2*tig + 1) ^ g) * 16;
        uint4 bqA[2], bqB[2];

        {
            const char* row = sB + (wn + 0*8 + g)*128;
            bqA[0] = *reinterpret_cast<const uint4*>(row + qa0);
            bqA[1] = *reinterpret_cast<const uint4*>(row + qa1);
        }

        #pragma unroll
        for (int ni = 0; ni < 8; ni++){
            if (ni < 7){
                const char* row = sB + (wn + (ni+1)*8 + g)*128;
                if (ni & 1){
                    bqA[0] = *reinterpret_cast<const uint4*>(row + qa0);
                    bqA[1] = *reinterpret_cast<const uint4*>(row + qa1);
                } else {
                    bqB[0] = *reinterpret_cast<const uint4*>(row + qa0);
                    bqB[1] = *reinterpret_cast<const uint4*>(row + qa1);
                }
            }
            const uint4* q = (ni & 1) ? bqB : bqA;
            unsigned b0[4], b1[4];
            b0[0] = q[0].x; b1[0] = q[0].y;      // ks = 0
            b0[1] = q[0].z; b1[1] = q[0].w;      // ks = 1
            b0[2] = q[1].x; b1[2] = q[1].y;      // ks = 2
            b0[3] = q[1].z; b1[3] = q[1].w;      // ks = 3
            #pragma unroll
            for (int ks = 0; ks < 4; ks++)
                #pragma unroll
                for (int mi = 0; mi < 4; mi++){
                    asm volatile(
                        "mma.sync.aligned.m16n8k8.row.col.f32.tf32.tf32.f32 "
                        "{%0,%1,%2,%3}, {%4,%5,%6,%7}, {%8,%9}, {%0,%1,%2,%3};\n"
                        : "+f"(acc[mi][ni][0]), "+f"(acc[mi][ni][1]),
                          "+f"(acc[mi][ni][2]), "+f"(acc[mi][ni][3])
                        : "r"(af[mi][ks].x), "r"(af[mi][ks].y),
                          "r"(af[mi][ks].z), "r"(af[mi][ks].w),
                          "r"(b0[ks]), "r"(b1[ks]));
                }
        }
    }

    // ---- epilogue: c0/c1 and c2/c3 are adjacent columns -> 8B stores ----
    float* outB = out + ((size_t)(b*256 + widm*64))*4096 + p0 + wn;
    #pragma unroll
    for (int mi = 0; mi < 4; mi++){
        #pragma unroll
        for (int ni = 0; ni < 8; ni++){
            int r0  = mi*16 + g;
            int col = ni*8 + 2*tig;
            float2 v0 = make_float2(acc[mi][ni][0], acc[mi][ni][1]);
            float2 v1 = make_float2(acc[mi][ni][2], acc[mi][ni][3]);
            *reinterpret_cast<float2*>(outB + (size_t)r0      *4096 + col) = v0;
            *reinterpret_cast<float2*>(outB + (size_t)(r0 + 8)*4096 + col) = v1;
        }
    }
}

// ---------------------------------------------------------------------------
extern "C" void kernel_launch(void* const* d_in, const int* in_sizes, int n_in,
                              void* d_out, int out_size)
{
    const float* inp = (const float*)d_in[0];   // [64,256,64,64] f32
    const float* act = (const float*)d_in[1];   // [64,9] f32
    const float* w   = (const float*)d_in[2];   // [256,256,3,3] f32
    float* out = (float*)d_out;

    cudaFuncSetAttribute(masc_conv_kernel,
                         cudaFuncAttributeMaxDynamicSharedMemorySize, SMEM_TOTAL);

    prep_mask_kernel<<<2, 32>>>(act);
    prep_wf_kernel<<<576, 256>>>(w);                    // 147456 float4
    prep_wfb_kernel<<<dim3(576, 64), 256>>>();          // 151 MB masked frags
    prep_x_kernel<<<dim3(128, 8, 64), dim3(32, 8)>>>(inp);
    masc_conv_kernel<<<dim3(32, 1, 64), 256, SMEM_TOTAL>>>(out);

    (void)in_sizes; (void)n_in; (void)out_size;
}

// round 14
// speedup vs baseline: 2.1313x; 1.2926x over previous
#include <cuda_runtime.h>
#include <cstdint>

// ---------------------------------------------------------------------------
// out[b,o,y,x] = sum_{t,i} softmax(a_b)[t] * W[o,i,t] * X[b,i,y+dy,x+dx]
// Implicit GEMM per batch: M=256 (one CTA), N=4096 pixels (32 tiles of 128),
// K=2304 = 9 taps x 256 ch, K-tile 32.  mma.sync.m16n8k8 TF32.
// A: per-batch mask-scaled prefragged tf32 W (151 MB gmem) -> 16B cp.async.
// B: NHWC tf32, permuted channel order -> 2x LDS.128 per n-tile, XOR swizzle.
// R13 change: NO __syncthreads in the mainloop.  Per-slot mbarrier
// producer/consumer pipeline (full: 256 cp-arrives; free: 8 warp-arrives)
// lets warps drift out of phase so the smem crossbar and the tensor pipe
// overlap instead of alternating in chip-wide bursts.
// ---------------------------------------------------------------------------

#define BM   256
#define BN   128
#define BK   32
#define NKT  72
#define NST  4
#define A_BYTES 32768                 // 2048 uint4: [widm4][mi4][ks4][lane32]
#define B_BYTES 16384                 // 128 rows x 128 B, permuted-k + XOR quads
#define STAGE_BYTES (A_BYTES + B_BYTES)
#define HDR  128
#define SMEM_TOTAL (HDR + NST*STAGE_BYTES)   // 196736 B

#define OFF_FULL 0                    // 4 mbarriers x 8 B
#define OFF_FREE 32                   // 4 mbarriers x 8 B

// Scratch (__device__ globals: allocation-free rule)
__device__ float g_Wf[NKT*8192];            // prefragged RAW fp32 W, 2.36 MB
__device__ float g_WfB[64ull*NKT*8192];     // per-batch masked tf32 frags, 151 MB
__device__ float g_Xt[64ull*4096*256];      // NHWC tf32, permuted-k, 256 MB
__device__ float g_mask[64*9];

__device__ __forceinline__ unsigned smem_u32(const void* p){
    return (unsigned)__cvta_generic_to_shared(p);
}
__device__ __forceinline__ void mbar_init(unsigned a, unsigned cnt){
    asm volatile("mbarrier.init.shared.b64 [%0], %1;" :: "r"(a), "r"(cnt) : "memory");
}
__device__ __forceinline__ void mbar_arrive(unsigned a){
    asm volatile("mbarrier.arrive.shared.b64 _, [%0];" :: "r"(a) : "memory");
}
__device__ __forceinline__ void cp_arrive_noinc(unsigned a){
    asm volatile("cp.async.mbarrier.arrive.noinc.shared.b64 [%0];" :: "r"(a) : "memory");
}
__device__ __forceinline__ void mbar_wait(unsigned a, unsigned ph){
    unsigned done;
    asm volatile("{\n\t.reg .pred p;\n\t"
        "mbarrier.try_wait.parity.acquire.cta.shared::cta.b64 p, [%1], %2;\n\t"
        "selp.b32 %0, 1, 0, p;\n\t}" : "=r"(done) : "r"(a), "r"(ph) : "memory");
    if (!done){
        asm volatile("{\n\t.reg .pred P1;\n\tW%=:\n\t"
            "mbarrier.try_wait.parity.acquire.cta.shared::cta.b64 P1, [%0], %1, 0x989680;\n\t"
            "@P1 bra.uni D%=;\n\tbra.uni W%=;\n\tD%=:\n\t}"
            :: "r"(a), "r"(ph) : "memory");
    }
}

// ---------------------------------------------------------------------------
__global__ void prep_mask_kernel(const float* __restrict__ act){
    int b = blockIdx.x * blockDim.x + threadIdx.x;
    if (b < 64){
        float v[9]; float mx = -3.4e38f;
        #pragma unroll
        for (int t = 0; t < 9; t++){ v[t] = act[b*9+t]; mx = fmaxf(mx, v[t]); }
        float s = 0.f;
        #pragma unroll
        for (int t = 0; t < 9; t++){ v[t] = expf(v[t]-mx); s += v[t]; }
        float inv = 1.f/s;
        #pragma unroll
        for (int t = 0; t < 9; t++) g_mask[b*9+t] = v[t]*inv;
    }
}

// W[o][i][t] -> fragment-order RAW fp32
__global__ void prep_wf_kernel(const float* __restrict__ w){
    int idx = blockIdx.x * blockDim.x + threadIdx.x;     // 147456 float4
    if (idx >= NKT*2048) return;
    int lane =  idx        & 31;
    int ks   = (idx >> 5)  & 3;
    int mi   = (idx >> 7)  & 3;
    int widm = (idx >> 9)  & 3;
    int kt   =  idx >> 11;
    int g = lane >> 2, tig = lane & 3;
    int m  = widm*64 + mi*16 + g;
    int t  = kt >> 3;
    int i0 = (kt & 7) * 32;
    int ia = i0 + ks*8 + tig;
    int ib = ia + 4;
    float4 v;
    v.x = w[(size_t)m    *2304 + ia*9 + t];
    v.y = w[(size_t)(m+8)*2304 + ia*9 + t];
    v.z = w[(size_t)m    *2304 + ib*9 + t];
    v.w = w[(size_t)(m+8)*2304 + ib*9 + t];
    reinterpret_cast<float4*>(g_Wf)[idx] = v;
}

// g_Wf (raw) x mask[b][t] -> g_WfB[b], tf32 (single rounding of m*w)
__global__ void prep_wfb_kernel(){
    int idx = blockIdx.x * blockDim.x + threadIdx.x;     // 0..147455
    int b   = blockIdx.y;
    int t   = idx >> 14;
    float mt = g_mask[b*9 + t];
    float4 v = reinterpret_cast<const float4*>(g_Wf)[idx];
    unsigned u0,u1,u2,u3;
    asm("cvt.rna.tf32.f32 %0, %1;" : "=r"(u0) : "f"(v.x*mt));
    asm("cvt.rna.tf32.f32 %0, %1;" : "=r"(u1) : "f"(v.y*mt));
    asm("cvt.rna.tf32.f32 %0, %1;" : "=r"(u2) : "f"(v.z*mt));
    asm("cvt.rna.tf32.f32 %0, %1;" : "=r"(u3) : "f"(v.w*mt));
    reinterpret_cast<uint4*>(g_WfB)[(size_t)b*(NKT*2048) + idx] =
        make_uint4(u0,u1,u2,u3);
}

// X[b][c][p] -> g_Xt[b][p][perm(c)], tf32.  perm within each 32-ch group:
// pos(kl) = (kl&3)*8 + ((kl>>3)&3)*2 + ((kl>>2)&1)
__global__ void prep_x_kernel(const float* __restrict__ inp){
    __shared__ float tile[32][33];
    int b = blockIdx.z, p0 = blockIdx.x*32, c0 = blockIdx.y*32;
    int tx = threadIdx.x, ty = threadIdx.y;              // (32, 8)
    const float* src = inp + (((size_t)b*256 + c0)*4096 + p0);
    #pragma unroll
    for (int r = 0; r < 4; r++)
        tile[ty + 8*r][tx] = src[(size_t)(ty + 8*r)*4096 + tx];
    __syncthreads();
    int pos = (tx&3)*8 + ((tx>>3)&3)*2 + ((tx>>2)&1);
    unsigned* dst = reinterpret_cast<unsigned*>(g_Xt) + (((size_t)b*4096 + p0)*256 + c0);
    #pragma unroll
    for (int r = 0; r < 4; r++){
        unsigned u;
        asm("cvt.rna.tf32.f32 %0, %1;" : "=r"(u) : "f"(tile[tx][ty + 8*r]));
        dst[(size_t)(ty + 8*r)*256 + pos] = u;
    }
}

// ---------------------------------------------------------------------------
__global__ void __launch_bounds__(256, 1) masc_conv_kernel(float* __restrict__ out)
{
    extern __shared__ char smem[];
    const unsigned sb = smem_u32(smem);
    const int tid  = threadIdx.x;
    const int lane = tid & 31;
    const int wid  = tid >> 5;
    const int widm = wid >> 1;          // 4 warps in M
    const int wn   = (wid & 1) * 64;    // 2 warps in N
    const int g    = lane >> 2;
    const int tig  = lane & 3;
    const int b    = blockIdx.z;
    const int p0   = blockIdx.x * BN;

    const float* xB = g_Xt + (size_t)b*4096*256;
    const uint4* aB = reinterpret_cast<const uint4*>(g_WfB) + (size_t)b*(NKT*2048);

    // B staging role: thread handles row n (pixel), 4 of 8 16B segments
    const int bn   = tid & 127;
    const int bs0  = (tid >> 7) * 4;

    // pipeline mbarriers
    if (tid < NST)                 mbar_init(sb + OFF_FULL + tid*8, 256);
    else if (tid >= 32 && tid < 32+NST) mbar_init(sb + OFF_FREE + (tid-32)*8, 8);
    asm volatile("fence.proxy.async.shared::cta;" ::: "memory");
    __syncthreads();

    float acc[4][8][4];
    #pragma unroll
    for (int mi = 0; mi < 4; mi++)
        #pragma unroll
        for (int ni = 0; ni < 8; ni++)
            #pragma unroll
            for (int r = 0; r < 4; r++) acc[mi][ni][r] = 0.f;

    // ---- stage one K-tile into slot s ----
    auto stage = [&](int kt, int s){
        const unsigned stg = sb + HDR + s*STAGE_BYTES;
        const uint4* srcA = aB + kt*2048;
        #pragma unroll
        for (int q = 0; q < 8; q++){
            int j = tid + 256*q;
            asm volatile("cp.async.cg.shared.global [%0], [%1], 16;\n"
                         :: "r"(stg + j*16), "l"(srcA + j));
        }
        const int t  = kt >> 3;
        const int i0 = (kt & 7) * 32;
        const int dy = t/3 - 1, dx = t%3 - 1;
        const int p  = p0 + bn;
        const int y  = (p >> 6) + dy;
        const int x  = (p & 63) + dx;
        const bool valid = ((unsigned)y < 64u) & ((unsigned)x < 64u);
        const float* srow = xB + ((size_t)(valid ? (y*64 + x) : 0)*256 + i0);
        const int sz = valid ? 16 : 0;
        const unsigned rowDst = stg + A_BYTES + bn*128;
        #pragma unroll
        for (int q = 0; q < 4; q++){
            int sgi = bs0 + q;
            unsigned dst = rowDst + ((sgi ^ (bn & 7)) * 16);
            asm volatile("cp.async.cg.shared.global [%0], [%1], 16, %2;\n"
                         :: "r"(dst), "l"(srow + sgi*4), "r"(sz));
        }
        cp_arrive_noinc(sb + OFF_FULL + s*8);   // full[s] when copies land
    };

    // ---- prologue: fill slots 0..2 (round 0, no free-wait) ----
    stage(0, 0);
    stage(1, 1);
    stage(2, 2);

    // ---- main loop: NO __syncthreads; warps drift within the slot window --
    #pragma unroll 1
    for (int kt = 0; kt < NKT; kt++){
        // produce slot for kt+3 (wait for its previous consumers first)
        const int kn = kt + 3;
        if (kn < NKT){
            const int sn = kn & 3, rn = kn >> 2;
            if (rn > 0) mbar_wait(sb + OFF_FREE + sn*8, (rn - 1) & 1);
            stage(kn, sn);
        }

        // consume slot kt
        const int s = kt & 3;
        mbar_wait(sb + OFF_FULL + s*8, (kt >> 2) & 1);

        const char* stg = smem + HDR + s*STAGE_BYTES;
        const uint4* sA = reinterpret_cast<const uint4*>(stg);
        const char*  sB = stg + A_BYTES;

        // A frags: 16x LDS.128
        uint4 af[4][4];
        #pragma unroll
        for (int mi = 0; mi < 4; mi++)
            #pragma unroll
            for (int ks = 0; ks < 4; ks++)
                af[mi][ks] = sA[((widm*4 + mi)*4 + ks)*32 + lane];

        // B frags: 2 LDS.128 per n-tile, ping-pong prefetch
        const unsigned qa0 = ((2*tig    ) ^ g) * 16;
        const unsigned qa1 = ((2*tig + 1) ^ g) * 16;
        uint4 bqA[2], bqB[2];
        {
            const char* row = sB + (wn + 0*8 + g)*128;
            bqA[0] = *reinterpret_cast<const uint4*>(row + qa0);
            bqA[1] = *reinterpret_cast<const uint4*>(row + qa1);
        }

        #pragma unroll
        for (int ni = 0; ni < 8; ni++){
            if (ni < 7){
                const char* row = sB + (wn + (ni+1)*8 + g)*128;
                if (ni & 1){
                    bqA[0] = *reinterpret_cast<const uint4*>(row + qa0);
                    bqA[1] = *reinterpret_cast<const uint4*>(row + qa1);
                } else {
                    bqB[0] = *reinterpret_cast<const uint4*>(row + qa0);
                    bqB[1] = *reinterpret_cast<const uint4*>(row + qa1);
                }
            }
            const uint4* q = (ni & 1) ? bqB : bqA;
            unsigned b0[4], b1[4];
            b0[0] = q[0].x; b1[0] = q[0].y;
            b0[1] = q[0].z; b1[1] = q[0].w;
            b0[2] = q[1].x; b1[2] = q[1].y;
            b0[3] = q[1].z; b1[3] = q[1].w;
            #pragma unroll
            for (int ks = 0; ks < 4; ks++)
                #pragma unroll
                for (int mi = 0; mi < 4; mi++){
                    asm volatile(
                        "mma.sync.aligned.m16n8k8.row.col.f32.tf32.tf32.f32 "
                        "{%0,%1,%2,%3}, {%4,%5,%6,%7}, {%8,%9}, {%0,%1,%2,%3};\n"
                        : "+f"(acc[mi][ni][0]), "+f"(acc[mi][ni][1]),
                          "+f"(acc[mi][ni][2]), "+f"(acc[mi][ni][3])
                        : "r"(af[mi][ks].x), "r"(af[mi][ks].y),
                          "r"(af[mi][ks].z), "r"(af[mi][ks].w),
                          "r"(b0[ks]), "r"(b1[ks]));
                }
        }

        // all lanes' LDS data consumed by mma.sync -> warp releases the slot
        if (lane == 0) mbar_arrive(sb + OFF_FREE + s*8);
    }

    // ---- epilogue: c0/c1 and c2/c3 are adjacent columns -> 8B stores ----
    float* outB = out + ((size_t)(b*256 + widm*64))*4096 + p0 + wn;
    #pragma unroll
    for (int mi = 0; mi < 4; mi++){
        #pragma unroll
        for (int ni = 0; ni < 8; ni++){
            int r0  = mi*16 + g;
            int col = ni*8 + 2*tig;
            float2 v0 = make_float2(acc[mi][ni][0], acc[mi][ni][1]);
            float2 v1 = make_float2(acc[mi][ni][2], acc[mi][ni][3]);
            *reinterpret_cast<float2*>(outB + (size_t)r0      *4096 + col) = v0;
            *reinterpret_cast<float2*>(outB + (size_t)(r0 + 8)*4096 + col) = v1;
        }
    }
}

// ---------------------------------------------------------------------------
extern "C" void kernel_launch(void* const* d_in, const int* in_sizes, int n_in,
                              void* d_out, int out_size)
{
    const float* inp = (const float*)d_in[0];   // [64,256,64,64] f32
    const float* act = (const float*)d_in[1];   // [64,9] f32
    const float* w   = (const float*)d_in[2];   // [256,256,3,3] f32
    float* out = (float*)d_out;

    cudaFuncSetAttribute(masc_conv_kernel,
                         cudaFuncAttributeMaxDynamicSharedMemorySize, SMEM_TOTAL);

    prep_mask_kernel<<<2, 32>>>(act);
    prep_wf_kernel<<<576, 256>>>(w);                    // 147456 float4
    prep_wfb_kernel<<<dim3(576, 64), 256>>>();          // 151 MB masked frags
    prep_x_kernel<<<dim3(128, 8, 64), dim3(32, 8)>>>(inp);
    masc_conv_kernel<<<dim3(32, 1, 64), 256, SMEM_TOTAL>>>(out);

    (void)in_sizes; (void)n_in; (void)out_size;
}

// round 16
// speedup vs baseline: 2.2496x; 1.0555x over previous
#include <cuda_runtime.h>
#include <cstdint>

// ---------------------------------------------------------------------------
// out[b,o,y,x] = sum_{t,i} softmax(a_b)[t] * W[o,i,t] * X[b,i,y+dy,x+dx]
// Implicit GEMM per batch: M=256 (one CTA), N=4096 pixels (32 tiles of 128),
// K=2304 = 9 taps x 256 ch, K-tile 32.  mma.sync.m16n8k8 TF32.
// A: per-batch mask-scaled prefragged tf32 W (151 MB gmem) -> 16B cp.async.
// B: NHWC tf32, permuted channel order -> 2x LDS.128 per n-tile, XOR swizzle.
// mbarrier producer/consumer ring (R13 structure, canonical slot order).
// R16: SMSP de-mirroring WITHOUT slot rotation (R15 deadlocked): warps 0-3
// produce-then-consume, warps 4-7 consume-then-produce.  Identical protocol,
// only intra-iteration position of the staging burst differs, so partner
// warps on one SMSP stop executing LDS bursts / MMA bursts in lock-step.
// ---------------------------------------------------------------------------

#define BM   256
#define BN   128
#define BK   32
#define NKT  72
#define NST  4
#define A_BYTES 32768                 // 2048 uint4: [widm4][mi4][ks4][lane32]
#define B_BYTES 16384                 // 128 rows x 128 B, permuted-k + XOR quads
#define STAGE_BYTES (A_BYTES + B_BYTES)
#define HDR  128
#define SMEM_TOTAL (HDR + NST*STAGE_BYTES)   // 196736 B

#define OFF_FULL 0                    // 4 mbarriers x 8 B
#define OFF_FREE 32                   // 4 mbarriers x 8 B

// Scratch (__device__ globals: allocation-free rule)
__device__ float g_Wf[NKT*8192];            // prefragged RAW fp32 W, 2.36 MB
__device__ float g_WfB[64ull*NKT*8192];     // per-batch masked tf32 frags, 151 MB
__device__ float g_Xt[64ull*4096*256];      // NHWC tf32, permuted-k, 256 MB
__device__ float g_mask[64*9];

__device__ __forceinline__ unsigned smem_u32(const void* p){
    return (unsigned)__cvta_generic_to_shared(p);
}
__device__ __forceinline__ void mbar_init(unsigned a, unsigned cnt){
    asm volatile("mbarrier.init.shared.b64 [%0], %1;" :: "r"(a), "r"(cnt) : "memory");
}
__device__ __forceinline__ void mbar_arrive(unsigned a){
    asm volatile("mbarrier.arrive.shared.b64 _, [%0];" :: "r"(a) : "memory");
}
__device__ __forceinline__ void cp_arrive_noinc(unsigned a){
    asm volatile("cp.async.mbarrier.arrive.noinc.shared.b64 [%0];" :: "r"(a) : "memory");
}
__device__ __forceinline__ void mbar_wait(unsigned a, unsigned ph){
    unsigned done;
    asm volatile("{\n\t.reg .pred p;\n\t"
        "mbarrier.try_wait.parity.acquire.cta.shared::cta.b64 p, [%1], %2;\n\t"
        "selp.b32 %0, 1, 0, p;\n\t}" : "=r"(done) : "r"(a), "r"(ph) : "memory");
    if (!done){
        asm volatile("{\n\t.reg .pred P1;\n\tW%=:\n\t"
            "mbarrier.try_wait.parity.acquire.cta.shared::cta.b64 P1, [%0], %1, 0x989680;\n\t"
            "@P1 bra.uni D%=;\n\tbra.uni W%=;\n\tD%=:\n\t}"
            :: "r"(a), "r"(ph) : "memory");
    }
}
// relaxed: ONLY for producer free-waits (post-wait accesses are cp.async writes)
__device__ __forceinline__ void mbar_wait_relaxed(unsigned a, unsigned ph){
    unsigned done;
    asm volatile("{\n\t.reg .pred p;\n\t"
        "mbarrier.try_wait.parity.relaxed.cta.shared::cta.b64 p, [%1], %2;\n\t"
        "selp.b32 %0, 1, 0, p;\n\t}" : "=r"(done) : "r"(a), "r"(ph) : "memory");
    if (!done){
        asm volatile("{\n\t.reg .pred P1;\n\tW%=:\n\t"
            "mbarrier.try_wait.parity.relaxed.cta.shared::cta.b64 P1, [%0], %1, 0x989680;\n\t"
            "@P1 bra.uni D%=;\n\tbra.uni W%=;\n\tD%=:\n\t}"
            :: "r"(a), "r"(ph) : "memory");
    }
}

// ---------------------------------------------------------------------------
__global__ void prep_mask_kernel(const float* __restrict__ act){
    int b = blockIdx.x * blockDim.x + threadIdx.x;
    if (b < 64){
        float v[9]; float mx = -3.4e38f;
        #pragma unroll
        for (int t = 0; t < 9; t++){ v[t] = act[b*9+t]; mx = fmaxf(mx, v[t]); }
        float s = 0.f;
        #pragma unroll
        for (int t = 0; t < 9; t++){ v[t] = expf(v[t]-mx); s += v[t]; }
        float inv = 1.f/s;
        #pragma unroll
        for (int t = 0; t < 9; t++) g_mask[b*9+t] = v[t]*inv;
    }
}

// W[o][i][t] -> fragment-order RAW fp32
__global__ void prep_wf_kernel(const float* __restrict__ w){
    int idx = blockIdx.x * blockDim.x + threadIdx.x;     // 147456 float4
    if (idx >= NKT*2048) return;
    int lane =  idx        & 31;
    int ks   = (idx >> 5)  & 3;
    int mi   = (idx >> 7)  & 3;
    int widm = (idx >> 9)  & 3;
    int kt   =  idx >> 11;
    int g = lane >> 2, tig = lane & 3;
    int m  = widm*64 + mi*16 + g;
    int t  = kt >> 3;
    int i0 = (kt & 7) * 32;
    int ia = i0 + ks*8 + tig;
    int ib = ia + 4;
    float4 v;
    v.x = w[(size_t)m    *2304 + ia*9 + t];
    v.y = w[(size_t)(m+8)*2304 + ia*9 + t];
    v.z = w[(size_t)m    *2304 + ib*9 + t];
    v.w = w[(size_t)(m+8)*2304 + ib*9 + t];
    reinterpret_cast<float4*>(g_Wf)[idx] = v;
}

// g_Wf (raw) x mask[b][t] -> g_WfB[b], tf32 (single rounding of m*w)
__global__ void prep_wfb_kernel(){
    int idx = blockIdx.x * blockDim.x + threadIdx.x;     // 0..147455
    int b   = blockIdx.y;
    int t   = idx >> 14;
    float mt = g_mask[b*9 + t];
    float4 v = reinterpret_cast<const float4*>(g_Wf)[idx];
    unsigned u0,u1,u2,u3;
    asm("cvt.rna.tf32.f32 %0, %1;" : "=r"(u0) : "f"(v.x*mt));
    asm("cvt.rna.tf32.f32 %0, %1;" : "=r"(u1) : "f"(v.y*mt));
    asm("cvt.rna.tf32.f32 %0, %1;" : "=r"(u2) : "f"(v.z*mt));
    asm("cvt.rna.tf32.f32 %0, %1;" : "=r"(u3) : "f"(v.w*mt));
    reinterpret_cast<uint4*>(g_WfB)[(size_t)b*(NKT*2048) + idx] =
        make_uint4(u0,u1,u2,u3);
}

// X[b][c][p] -> g_Xt[b][p][perm(c)], tf32.  perm within each 32-ch group:
// pos(kl) = (kl&3)*8 + ((kl>>3)&3)*2 + ((kl>>2)&1)
__global__ void prep_x_kernel(const float* __restrict__ inp){
    __shared__ float tile[32][33];
    int b = blockIdx.z, p0 = blockIdx.x*32, c0 = blockIdx.y*32;
    int tx = threadIdx.x, ty = threadIdx.y;              // (32, 8)
    const float* src = inp + (((size_t)b*256 + c0)*4096 + p0);
    #pragma unroll
    for (int r = 0; r < 4; r++)
        tile[ty + 8*r][tx] = src[(size_t)(ty + 8*r)*4096 + tx];
    __syncthreads();
    int pos = (tx&3)*8 + ((tx>>3)&3)*2 + ((tx>>2)&1);
    unsigned* dst = reinterpret_cast<unsigned*>(g_Xt) + (((size_t)b*4096 + p0)*256 + c0);
    #pragma unroll
    for (int r = 0; r < 4; r++){
        unsigned u;
        asm("cvt.rna.tf32.f32 %0, %1;" : "=r"(u) : "f"(tile[tx][ty + 8*r]));
        dst[(size_t)(ty + 8*r)*256 + pos] = u;
    }
}

// ---------------------------------------------------------------------------
__global__ void __launch_bounds__(256, 1) masc_conv_kernel(float* __restrict__ out)
{
    extern __shared__ char smem[];
    const unsigned sb = smem_u32(smem);
    const int tid  = threadIdx.x;
    const int lane = tid & 31;
    const int wid  = tid >> 5;
    const int widm = wid >> 1;          // 4 warps in M
    const int wn   = (wid & 1) * 64;    // 2 warps in N
    const int g    = lane >> 2;
    const int tig  = lane & 3;
    const int b    = blockIdx.z;
    const int p0   = blockIdx.x * BN;
    // SMSP partner de-mirroring (deadlock-free): warps 0-3 produce BEFORE
    // consuming, warps 4-7 produce AFTER.  Same slots/counts/parities.
    const bool prodFirst = ((wid >> 2) & 1) == 0;

    const float* xB = g_Xt + (size_t)b*4096*256;
    const uint4* aB = reinterpret_cast<const uint4*>(g_WfB) + (size_t)b*(NKT*2048);

    // B staging role: thread handles row n (pixel), 4 of 8 16B segments
    const int bn   = tid & 127;
    const int bs0  = (tid >> 7) * 4;

    // pipeline mbarriers
    if (tid < NST)                 mbar_init(sb + OFF_FULL + tid*8, 256);
    else if (tid >= 32 && tid < 32+NST) mbar_init(sb + OFF_FREE + (tid-32)*8, 8);
    asm volatile("fence.proxy.async.shared::cta;" ::: "memory");
    __syncthreads();

    float acc[4][8][4];
    #pragma unroll
    for (int mi = 0; mi < 4; mi++)
        #pragma unroll
        for (int ni = 0; ni < 8; ni++)
            #pragma unroll
            for (int r = 0; r < 4; r++) acc[mi][ni][r] = 0.f;

    // ---- stage one K-tile into slot s ----
    auto stage = [&](int kt, int s){
        const unsigned stg = sb + HDR + s*STAGE_BYTES;
        const uint4* srcA = aB + kt*2048;
        #pragma unroll
        for (int q = 0; q < 8; q++){
            int j = tid + 256*q;
            asm volatile("cp.async.cg.shared.global [%0], [%1], 16;\n"
                         :: "r"(stg + j*16), "l"(srcA + j));
        }
        const int t  = kt >> 3;
        const int i0 = (kt & 7) * 32;
        const int dy = t/3 - 1, dx = t%3 - 1;
        const int p  = p0 + bn;
        const int y  = (p >> 6) + dy;
        const int x  = (p & 63) + dx;
        const bool valid = ((unsigned)y < 64u) & ((unsigned)x < 64u);
        const float* srow = xB + ((size_t)(valid ? (y*64 + x) : 0)*256 + i0);
        const int sz = valid ? 16 : 0;
        const unsigned rowDst = stg + A_BYTES + bn*128;
        #pragma unroll
        for (int q = 0; q < 4; q++){
            int sgi = bs0 + q;
            unsigned dst = rowDst + ((sgi ^ (bn & 7)) * 16);
            asm volatile("cp.async.cg.shared.global [%0], [%1], 16, %2;\n"
                         :: "r"(dst), "l"(srow + sgi*4), "r"(sz));
        }
        cp_arrive_noinc(sb + OFF_FULL + s*8);   // full[s] when copies land
    };

    // produce canonical slot kt+3 (with backpressure wait)
    auto produce = [&](int kt){
        const int kn = kt + 3;
        if (kn < NKT){
            const int sn = kn & 3, rn = kn >> 2;
            if (rn > 0) mbar_wait_relaxed(sb + OFF_FREE + sn*8, (rn - 1) & 1);
            stage(kn, sn);
        }
    };

    // consume slot kt: full-wait, LDS frags, 128 HMMA, free-arrive
    auto consume = [&](int kt){
        const int s = kt & 3;
        mbar_wait(sb + OFF_FULL + s*8, (kt >> 2) & 1);

        const char* stg = smem + HDR + s*STAGE_BYTES;
        const uint4* sA = reinterpret_cast<const uint4*>(stg);
        const char*  sB = stg + A_BYTES;

        // A frags: 16x LDS.128
        uint4 af[4][4];
        #pragma unroll
        for (int mi = 0; mi < 4; mi++)
            #pragma unroll
            for (int ks = 0; ks < 4; ks++)
                af[mi][ks] = sA[((widm*4 + mi)*4 + ks)*32 + lane];

        // B frags: 2 LDS.128 per n-tile, ping-pong prefetch
        const unsigned qa0 = ((2*tig    ) ^ g) * 16;
        const unsigned qa1 = ((2*tig + 1) ^ g) * 16;
        uint4 bqA[2], bqB[2];
        {
            const char* row = sB + (wn + 0*8 + g)*128;
            bqA[0] = *reinterpret_cast<const uint4*>(row + qa0);
            bqA[1] = *reinterpret_cast<const uint4*>(row + qa1);
        }

        #pragma unroll
        for (int ni = 0; ni < 8; ni++){
            if (ni < 7){
                const char* row = sB + (wn + (ni+1)*8 + g)*128;
                if (ni & 1){
                    bqA[0] = *reinterpret_cast<const uint4*>(row + qa0);
                    bqA[1] = *reinterpret_cast<const uint4*>(row + qa1);
                } else {
                    bqB[0] = *reinterpret_cast<const uint4*>(row + qa0);
                    bqB[1] = *reinterpret_cast<const uint4*>(row + qa1);
                }
            }
            const uint4* q = (ni & 1) ? bqB : bqA;
            unsigned b0[4], b1[4];
            b0[0] = q[0].x; b1[0] = q[0].y;
            b0[1] = q[0].z; b1[1] = q[0].w;
            b0[2] = q[1].x; b1[2] = q[1].y;
            b0[3] = q[1].z; b1[3] = q[1].w;
            #pragma unroll
            for (int ks = 0; ks < 4; ks++)
                #pragma unroll
                for (int mi = 0; mi < 4; mi++){
                    asm volatile(
                        "mma.sync.aligned.m16n8k8.row.col.f32.tf32.tf32.f32 "
                        "{%0,%1,%2,%3}, {%4,%5,%6,%7}, {%8,%9}, {%0,%1,%2,%3};\n"
                        : "+f"(acc[mi][ni][0]), "+f"(acc[mi][ni][1]),
                          "+f"(acc[mi][ni][2]), "+f"(acc[mi][ni][3])
                        : "r"(af[mi][ks].x), "r"(af[mi][ks].y),
                          "r"(af[mi][ks].z), "r"(af[mi][ks].w),
                          "r"(b0[ks]), "r"(b1[ks]));
                }
        }

        // all lanes' LDS data consumed by mma.sync -> warp releases the slot
        if (lane == 0) mbar_arrive(sb + OFF_FREE + s*8);
    };

    // ---- prologue: fill slots 0..2 (round 0, no free-wait) ----
    stage(0, 0);
    stage(1, 1);
    stage(2, 2);

    // ---- main loop: canonical order, staggered produce position ----
    if (prodFirst){
        #pragma unroll 1
        for (int kt = 0; kt < NKT; kt++){ produce(kt); consume(kt); }
    } else {
        #pragma unroll 1
        for (int kt = 0; kt < NKT; kt++){ consume(kt); produce(kt); }
    }

    // ---- epilogue: c0/c1 and c2/c3 are adjacent columns -> 8B stores ----
    float* outB = out + ((size_t)(b*256 + widm*64))*4096 + p0 + wn;
    #pragma unroll
    for (int mi = 0; mi < 4; mi++){
        #pragma unroll
        for (int ni = 0; ni < 8; ni++){
            int r0  = mi*16 + g;
            int col = ni*8 + 2*tig;
            float2 v0 = make_float2(acc[mi][ni][0], acc[mi][ni][1]);
            float2 v1 = make_float2(acc[mi][ni][2], acc[mi][ni][3]);
            *reinterpret_cast<float2*>(outB + (size_t)r0      *4096 + col) = v0;
            *reinterpret_cast<float2*>(outB + (size_t)(r0 + 8)*4096 + col) = v1;
        }
    }
}

// ---------------------------------------------------------------------------
extern "C" void kernel_launch(void* const* d_in, const int* in_sizes, int n_in,
                              void* d_out, int out_size)
{
    const float* inp = (const float*)d_in[0];   // [64,256,64,64] f32
    const float* act = (const float*)d_in[1];   // [64,9] f32
    const float* w   = (const float*)d_in[2];   // [256,256,3,3] f32
    float* out = (float*)d_out;

    cudaFuncSetAttribute(masc_conv_kernel,
                         cudaFuncAttributeMaxDynamicSharedMemorySize, SMEM_TOTAL);

    prep_mask_kernel<<<2, 32>>>(act);
    prep_wf_kernel<<<576, 256>>>(w);                    // 147456 float4
    prep_wfb_kernel<<<dim3(576, 64), 256>>>();          // 151 MB masked frags
    prep_x_kernel<<<dim3(128, 8, 64), dim3(32, 8)>>>(inp);
    masc_conv_kernel<<<dim3(32, 1, 64), 256, SMEM_TOTAL>>>(out);

    (void)in_sizes; (void)n_in; (void)out_size;
}